// round 1
// baseline (speedup 1.0000x reference)
#include <cuda_runtime.h>
#include <cstdint>

// Problem shape (fixed by the dataset)
#define NMAX 50000
#define EMAX 1600000
#define D    128

// Scratch (static __device__ — no allocation allowed)
__device__ float g_xn[(size_t)NMAX * D];   // normalized features (25.6 MB, fits L2)
__device__ float g_logits[EMAX];           // per-edge logit, later exp(logit-m)
__device__ float g_m[NMAX];                // segment max  (init = self-loop logit)
__device__ float g_s[NMAX];                // segment sum of exp
__device__ float g_self[NMAX];             // self-loop logit, later exp(self-m)
__device__ int   g_is64;                   // edge_index element width flag

// ---------------------------------------------------------------------------
// helpers
// ---------------------------------------------------------------------------
__device__ __forceinline__ long long ld_idx(const void* p, long long pos, int is64) {
    if (is64) return ((const long long*)p)[pos];
    return (long long)((const int*)p)[pos];
}

// float atomic max via ordered-int trick (valid for mixed signs)
__device__ __forceinline__ void atomicMaxFloat(float* addr, float v) {
    if (v >= 0.0f) atomicMax((int*)addr, __float_as_int(v));
    else           atomicMin((unsigned int*)addr, __float_as_uint(v));
}

// vector reduction (no return) — 1 instruction for 4 floats, sm_90+
__device__ __forceinline__ void red_add_v4(float* p, float a, float b, float c, float d) {
    asm volatile("red.global.add.v4.f32 [%0], {%1, %2, %3, %4};"
                 :: "l"(p), "f"(a), "f"(b), "f"(c), "f"(d) : "memory");
}

// ---------------------------------------------------------------------------
// K0: detect int32 vs int64 edge_index. Values < 50000, so if int64 every odd
// 32-bit word of the first 32 entries is 0; for random int32 indices that is
// impossible.
// ---------------------------------------------------------------------------
__global__ void k_detect(const unsigned int* __restrict__ w) {
    int is64 = 1;
    #pragma unroll
    for (int i = 1; i < 64; i += 2)
        if (w[i] != 0u) { is64 = 0; break; }
    g_is64 = is64;
}

// ---------------------------------------------------------------------------
// K1: row-normalize x -> g_xn, init self-loop logit and running max.
// One warp per node row; float4 per lane.
// ---------------------------------------------------------------------------
__global__ void k_normalize(const float* __restrict__ x,
                            const float* __restrict__ beta, int N) {
    int w = (blockIdx.x * blockDim.x + threadIdx.x) >> 5;
    if (w >= N) return;
    int lane = threadIdx.x & 31;
    float4 v = ((const float4*)(x + (long long)w * D))[lane];
    float ss = v.x * v.x + v.y * v.y + v.z * v.z + v.w * v.w;
    #pragma unroll
    for (int o = 16; o; o >>= 1) ss += __shfl_xor_sync(0xffffffffu, ss, o);
    float inv = rsqrtf(fmaxf(ss, 1e-24f));       // EPS^2 = (1e-12)^2
    float4 o4 = make_float4(v.x * inv, v.y * inv, v.z * inv, v.w * inv);
    ((float4*)(g_xn + (long long)w * D))[lane] = o4;
    if (lane == 0) {
        float selfdot = ss * inv * inv;          // == sum(xn^2), exact per reference
        float sl = beta[0] * selfdot;
        g_self[w] = sl;
        g_m[w]    = sl;                          // max init includes self-loop
    }
}

// ---------------------------------------------------------------------------
// K2: per-edge cosine logit + running segment max. One warp per edge.
// ---------------------------------------------------------------------------
__global__ void k_edge_logit(const void* __restrict__ idx,
                             const float* __restrict__ beta, int E) {
    int e = (blockIdx.x * blockDim.x + threadIdx.x) >> 5;
    if (e >= E) return;
    int lane = threadIdx.x & 31;
    int is64 = g_is64;
    long long src = ld_idx(idx, e, is64);
    long long dst = ld_idx(idx, (long long)E + e, is64);
    float4 a = ((const float4*)(g_xn + src * D))[lane];
    float4 b = ((const float4*)(g_xn + dst * D))[lane];
    float d = a.x * b.x + a.y * b.y + a.z * b.z + a.w * b.w;
    #pragma unroll
    for (int o = 16; o; o >>= 1) d += __shfl_xor_sync(0xffffffffu, d, o);
    if (lane == 0) {
        float logit = beta[0] * d;
        g_logits[e] = logit;
        atomicMaxFloat(&g_m[(int)dst], logit);
    }
}

// ---------------------------------------------------------------------------
// K3a: per-node: self exp numerator + sum init
// ---------------------------------------------------------------------------
__global__ void k_s_init(int N) {
    int i = blockIdx.x * blockDim.x + threadIdx.x;
    if (i >= N) return;
    float e0 = __expf(g_self[i] - g_m[i]);
    g_self[i] = e0;   // numerator for self edge
    g_s[i]    = e0;   // sum init
}

// ---------------------------------------------------------------------------
// K3b: per-edge: w = exp(logit - m[dst]); accumulate segment sum.
// ---------------------------------------------------------------------------
__global__ void k_edge_sum(const void* __restrict__ idx, int E) {
    int e = blockIdx.x * blockDim.x + threadIdx.x;
    if (e >= E) return;
    int is64 = g_is64;
    long long dst = ld_idx(idx, (long long)E + e, is64);
    float w = __expf(g_logits[e] - g_m[(int)dst]);
    g_logits[e] = w;
    atomicAdd(&g_s[(int)dst], w);
}

// ---------------------------------------------------------------------------
// K4a: init out with self-loop contribution: out[i] = (e_self/s) * x[i]
// ---------------------------------------------------------------------------
__global__ void k_self_out(const float* __restrict__ x,
                           float* __restrict__ out, int N) {
    int w = (blockIdx.x * blockDim.x + threadIdx.x) >> 5;
    if (w >= N) return;
    int lane = threadIdx.x & 31;
    float coef = g_self[w] / g_s[w];
    float4 v = ((const float4*)(x + (long long)w * D))[lane];
    ((float4*)(out + (long long)w * D))[lane] =
        make_float4(coef * v.x, coef * v.y, coef * v.z, coef * v.w);
}

// ---------------------------------------------------------------------------
// K4b: per-edge scatter: out[dst] += (w/s[dst]) * x[src]. One warp per edge,
// vector RED (4 floats / instruction).
// ---------------------------------------------------------------------------
__global__ void k_edge_scatter(const float* __restrict__ x,
                               const void* __restrict__ idx,
                               float* __restrict__ out, int E) {
    int e = (blockIdx.x * blockDim.x + threadIdx.x) >> 5;
    if (e >= E) return;
    int lane = threadIdx.x & 31;
    int is64 = g_is64;
    long long src = ld_idx(idx, e, is64);
    long long dst = ld_idx(idx, (long long)E + e, is64);
    float coef = g_logits[e] / g_s[(int)dst];
    float4 v = ((const float4*)(x + src * D))[lane];
    float* p = out + dst * D + lane * 4;
    red_add_v4(p, coef * v.x, coef * v.y, coef * v.z, coef * v.w);
}

// ---------------------------------------------------------------------------
// K5: ReLU in place
// ---------------------------------------------------------------------------
__global__ void k_relu(float* __restrict__ out, int n) {
    int i = blockIdx.x * blockDim.x + threadIdx.x;
    if (i >= n) return;
    out[i] = fmaxf(out[i], 0.0f);
}

// ---------------------------------------------------------------------------
extern "C" void kernel_launch(void* const* d_in, const int* in_sizes, int n_in,
                              void* d_out, int out_size) {
    const float* x    = (const float*)d_in[0];
    const float* beta = (const float*)d_in[1];
    const void*  idx  = d_in[2];
    float* out = (float*)d_out;

    int N = in_sizes[0] / D;
    int E = in_sizes[2] / 2;

    const int T = 256;
    k_detect<<<1, 1>>>((const unsigned int*)idx);
    k_normalize<<<(N * 32 + T - 1) / T, T>>>(x, beta, N);
    k_edge_logit<<<(int)(((long long)E * 32 + T - 1) / T), T>>>(idx, beta, E);
    k_s_init<<<(N + T - 1) / T, T>>>(N);
    k_edge_sum<<<(E + T - 1) / T, T>>>(idx, E);
    k_self_out<<<(N * 32 + T - 1) / T, T>>>(x, out, N);
    k_edge_scatter<<<(int)(((long long)E * 32 + T - 1) / T), T>>>(x, idx, out, E);
    k_relu<<<(N * D + T - 1) / T, T>>>(out, N * D);
}

// round 2
// speedup vs baseline: 2.1087x; 2.1087x over previous
#include <cuda_runtime.h>
#include <cstdint>

// Problem shape (fixed by the dataset)
#define NMAX 50000
#define EMAX 1600000
#define D    128

// Scratch (static __device__ — no allocation allowed)
__device__ int   g_is64;               // edge_index element width flag
__device__ int   g_deg[NMAX];          // in-degree histogram
__device__ int   g_rowptr[NMAX + 1];   // CSR row pointers (by dst)
__device__ int   g_cursor[NMAX];       // fill cursors (copy of rowptr)
__device__ int   g_esrc[EMAX];         // CSR: src node per incoming edge
__device__ float g_inv[NMAX];          // 1/||x_i|| (clamped)

// ---------------------------------------------------------------------------
// index helpers (handle int32 or int64 edge_index)
// ---------------------------------------------------------------------------
__device__ __forceinline__ int ld_src(const void* p, int e, int is64) {
    if (is64) return (int)((const long long*)p)[e];
    return ((const int*)p)[e];
}
__device__ __forceinline__ int ld_dst(const void* p, int e, int E, int is64) {
    if (is64) return (int)((const long long*)p)[(long long)E + e];
    return ((const int*)p)[E + e];
}

// ---------------------------------------------------------------------------
// K0: detect int32 vs int64 edge_index. Values < 50000, so if int64 every odd
// 32-bit word of the first 32 entries is 0; random int32 makes that impossible.
// ---------------------------------------------------------------------------
__global__ void k_detect(const unsigned int* __restrict__ w) {
    int is64 = 1;
    #pragma unroll
    for (int i = 1; i < 64; i += 2)
        if (w[i] != 0u) { is64 = 0; break; }
    g_is64 = is64;
}

// ---------------------------------------------------------------------------
// K1: zero the degree histogram
// ---------------------------------------------------------------------------
__global__ void k_zero(int N) {
    int i = blockIdx.x * blockDim.x + threadIdx.x;
    if (i < N) g_deg[i] = 0;
}

// ---------------------------------------------------------------------------
// K2: degree histogram over destinations
// ---------------------------------------------------------------------------
__global__ void k_hist(const void* __restrict__ idx, int E) {
    int e = blockIdx.x * blockDim.x + threadIdx.x;
    if (e >= E) return;
    int dst = ld_dst(idx, e, E, g_is64);
    atomicAdd(&g_deg[dst], 1);
}

// ---------------------------------------------------------------------------
// K3: exclusive prefix scan of g_deg -> g_rowptr (+ cursor copy). One block.
// ---------------------------------------------------------------------------
__global__ void k_scan(int N) {
    __shared__ int sh[1024];
    int t = threadIdx.x;
    int per = (N + 1023) / 1024;
    int base = t * per;

    int local = 0;
    for (int k = 0; k < per; k++) {
        int i = base + k;
        if (i < N) local += g_deg[i];
    }
    sh[t] = local;
    __syncthreads();

    // Hillis-Steele inclusive scan
    for (int off = 1; off < 1024; off <<= 1) {
        int v = (t >= off) ? sh[t - off] : 0;
        __syncthreads();
        sh[t] += v;
        __syncthreads();
    }
    int run = sh[t] - local;   // exclusive prefix for this chunk

    for (int k = 0; k < per; k++) {
        int i = base + k;
        if (i < N) {
            int d = g_deg[i];
            g_rowptr[i] = run;
            g_cursor[i] = run;
            run += d;
        }
    }
    if (t == 1023) g_rowptr[N] = sh[1023];
}

// ---------------------------------------------------------------------------
// K4: CSR fill — scatter src ids into per-dst buckets
// ---------------------------------------------------------------------------
__global__ void k_fill(const void* __restrict__ idx, int E) {
    int e = blockIdx.x * blockDim.x + threadIdx.x;
    if (e >= E) return;
    int is64 = g_is64;
    int src = ld_src(idx, e, is64);
    int dst = ld_dst(idx, e, E, is64);
    int p = atomicAdd(&g_cursor[dst], 1);
    g_esrc[p] = src;
}

// ---------------------------------------------------------------------------
// K5: inverse norms. One warp per node row; float4 per lane.
// ---------------------------------------------------------------------------
__global__ void k_invnorm(const float* __restrict__ x, int N) {
    int w = (blockIdx.x * blockDim.x + threadIdx.x) >> 5;
    if (w >= N) return;
    int lane = threadIdx.x & 31;
    float4 v = ((const float4*)x)[w * 32 + lane];
    float ss = v.x * v.x + v.y * v.y + v.z * v.z + v.w * v.w;
    #pragma unroll
    for (int o = 16; o; o >>= 1) ss += __shfl_xor_sync(0xffffffffu, ss, o);
    if (lane == 0)
        g_inv[w] = rsqrtf(fmaxf(ss, 1e-24f));   // EPS^2 = (1e-12)^2
}

// ---------------------------------------------------------------------------
// K6: fused gather. One warp per destination node:
//   out[i] = relu( (Σ_e w_e x_src + w_self x_i) / (Σ_e w_e + w_self) )
//   w_e = exp(beta * cos(x_src, x_i) - |beta|)   (shift-invariant softmax)
// Register accumulation, single output write, 1-deep src-row prefetch.
// ---------------------------------------------------------------------------
__global__ void k_gather(const float* __restrict__ x,
                         const float* __restrict__ beta,
                         float* __restrict__ out, int N) {
    int i = (blockIdx.x * blockDim.x + threadIdx.x) >> 5;
    if (i >= N) return;
    int lane = threadIdx.x & 31;

    const float4* X = (const float4*)x;
    float bta = beta[0];
    float B = fabsf(bta);
    float inv_i = g_inv[i];

    float4 a = X[i * 32 + lane];

    // self-loop term
    float ss = a.x * a.x + a.y * a.y + a.z * a.z + a.w * a.w;
    #pragma unroll
    for (int o = 16; o; o >>= 1) ss += __shfl_xor_sync(0xffffffffu, ss, o);
    float wv = __expf(bta * (ss * inv_i * inv_i) - B);
    float sum = wv;
    float4 acc = make_float4(wv * a.x, wv * a.y, wv * a.z, wv * a.w);

    int start = g_rowptr[i];
    int end   = g_rowptr[i + 1];
    if (start < end) {
        // prefetch first src row
        int s = g_esrc[start];
        float4 v = X[(long long)s * 32 + lane];
        float invs = g_inv[s];
        for (int j = start; j < end; j++) {
            float4 vc = v;
            float invc = invs;
            if (j + 1 < end) {            // prefetch next before the reduce chain
                s = g_esrc[j + 1];
                v = X[(long long)s * 32 + lane];
                invs = g_inv[s];
            }
            float d = a.x * vc.x + a.y * vc.y + a.z * vc.z + a.w * vc.w;
            #pragma unroll
            for (int o = 16; o; o >>= 1) d += __shfl_xor_sync(0xffffffffu, d, o);
            float w = __expf(bta * (d * inv_i * invc) - B);
            sum += w;
            acc.x += w * vc.x;
            acc.y += w * vc.y;
            acc.z += w * vc.z;
            acc.w += w * vc.w;
        }
    }

    float r = 1.0f / sum;
    float4 o4 = make_float4(fmaxf(acc.x * r, 0.0f), fmaxf(acc.y * r, 0.0f),
                            fmaxf(acc.z * r, 0.0f), fmaxf(acc.w * r, 0.0f));
    ((float4*)out)[i * 32 + lane] = o4;
}

// ---------------------------------------------------------------------------
extern "C" void kernel_launch(void* const* d_in, const int* in_sizes, int n_in,
                              void* d_out, int out_size) {
    const float* x    = (const float*)d_in[0];
    const float* beta = (const float*)d_in[1];
    const void*  idx  = d_in[2];
    float* out = (float*)d_out;

    int N = in_sizes[0] / D;
    int E = in_sizes[2] / 2;

    const int T = 256;
    k_detect <<<1, 1>>>((const unsigned int*)idx);
    k_zero   <<<(N + T - 1) / T, T>>>(N);
    k_hist   <<<(E + T - 1) / T, T>>>(idx, E);
    k_scan   <<<1, 1024>>>(N);
    k_fill   <<<(E + T - 1) / T, T>>>(idx, E);
    k_invnorm<<<(N * 32 + T - 1) / T, T>>>(x, N);
    k_gather <<<(N * 32 + T - 1) / T, T>>>(x, beta, out, N);
}

// round 3
// speedup vs baseline: 3.2042x; 1.5196x over previous
#include <cuda_runtime.h>
#include <cstdint>

// Problem shape (fixed by the dataset)
#define NMAX 50000
#define EMAX 1600000
#define D    128

// Scratch (static __device__ — no allocation allowed)
__device__ int   g_is64;                // edge_index element width flag
__device__ int   g_deg[NMAX];           // in-degree histogram
__device__ int   g_rowstart[NMAX];      // bucket start per dst
__device__ int   g_rowend[NMAX];        // bucket end per dst
__device__ int   g_cursor[NMAX];        // fill cursors
__device__ int   g_total;               // global bucket allocator
__device__ int   g_esrc[EMAX];          // CSR: src node per incoming edge
__device__ float g_inv[NMAX];           // 1/||x_i|| (clamped)

// ---------------------------------------------------------------------------
// index helpers (handle int32 or int64 edge_index)
// ---------------------------------------------------------------------------
__device__ __forceinline__ int ld_src(const void* p, int e, int is64) {
    if (is64) return (int)((const long long*)p)[e];
    return ((const int*)p)[e];
}
__device__ __forceinline__ int ld_dst(const void* p, int e, int E, int is64) {
    if (is64) return (int)((const long long*)p)[(long long)E + e];
    return ((const int*)p)[E + e];
}

// ---------------------------------------------------------------------------
// K0: detect int32 vs int64 edge_index. Values < 50000, so if int64 every odd
// 32-bit word of the first 32 entries is 0; random int32 makes that impossible.
// ---------------------------------------------------------------------------
__global__ void k_detect(const unsigned int* __restrict__ w) {
    int is64 = 1;
    #pragma unroll
    for (int i = 1; i < 64; i += 2)
        if (w[i] != 0u) { is64 = 0; break; }
    g_is64 = is64;
}

// ---------------------------------------------------------------------------
// K1: zero degree histogram + allocator
// ---------------------------------------------------------------------------
__global__ void k_zero(int N) {
    int i = blockIdx.x * blockDim.x + threadIdx.x;
    if (i < N) g_deg[i] = 0;
    if (i == 0) g_total = 0;
}

// ---------------------------------------------------------------------------
// K2: degree histogram over destinations
// ---------------------------------------------------------------------------
__global__ void k_hist(const void* __restrict__ idx, int E) {
    int e = blockIdx.x * blockDim.x + threadIdx.x;
    if (e >= E) return;
    int dst = ld_dst(idx, e, E, g_is64);
    atomicAdd(&g_deg[dst], 1);
}

// ---------------------------------------------------------------------------
// K3: decoupled bucket allocation. Per-block scan of 256 degrees (shuffle +
// shared), one global atomicAdd per block for the base. Bucket placement
// order is irrelevant to the output (gather only reads its own range).
// ---------------------------------------------------------------------------
__global__ void k_alloc(int N) {
    int i = blockIdx.x * blockDim.x + threadIdx.x;
    int lane = threadIdx.x & 31;
    int wid  = threadIdx.x >> 5;
    int d = (i < N) ? g_deg[i] : 0;

    // warp inclusive scan
    int v = d;
    #pragma unroll
    for (int o = 1; o < 32; o <<= 1) {
        int t = __shfl_up_sync(0xffffffffu, v, o);
        if (lane >= o) v += t;
    }

    __shared__ int wsum[8];
    __shared__ int base;
    if (lane == 31) wsum[wid] = v;
    __syncthreads();
    if (threadIdx.x == 0) {
        int tot = 0;
        #pragma unroll
        for (int k = 0; k < 8; k++) { int t = wsum[k]; wsum[k] = tot; tot += t; }
        base = atomicAdd(&g_total, tot);
    }
    __syncthreads();

    int start = base + wsum[wid] + v - d;   // exclusive prefix within block
    if (i < N) {
        g_rowstart[i] = start;
        g_cursor[i]   = start;
        g_rowend[i]   = start + d;
    }
}

// ---------------------------------------------------------------------------
// K4: CSR fill — scatter src ids into per-dst buckets
// ---------------------------------------------------------------------------
__global__ void k_fill(const void* __restrict__ idx, int E) {
    int e = blockIdx.x * blockDim.x + threadIdx.x;
    if (e >= E) return;
    int is64 = g_is64;
    int src = ld_src(idx, e, is64);
    int dst = ld_dst(idx, e, E, is64);
    int p = atomicAdd(&g_cursor[dst], 1);
    g_esrc[p] = src;
}

// ---------------------------------------------------------------------------
// K5: inverse norms. One warp per node row; float4 per lane.
// ---------------------------------------------------------------------------
__global__ void k_invnorm(const float* __restrict__ x, int N) {
    int w = (blockIdx.x * blockDim.x + threadIdx.x) >> 5;
    if (w >= N) return;
    int lane = threadIdx.x & 31;
    float4 v = ((const float4*)x)[w * 32 + lane];
    float ss = v.x * v.x + v.y * v.y + v.z * v.z + v.w * v.w;
    #pragma unroll
    for (int o = 16; o; o >>= 1) ss += __shfl_xor_sync(0xffffffffu, ss, o);
    if (lane == 0)
        g_inv[w] = rsqrtf(fmaxf(ss, 1e-24f));   // EPS^2 = (1e-12)^2
}

// ---------------------------------------------------------------------------
// K6: fused gather. One warp per destination node:
//   out[i] = relu( (Σ_e w_e x_src + w_self x_i) / (Σ_e w_e + w_self) )
//   w_e = exp(beta * cos(x_src, x_i) - |beta|)   (shift-invariant softmax)
// Register accumulation, single output write, 1-deep src-row prefetch.
// ---------------------------------------------------------------------------
__global__ void k_gather(const float* __restrict__ x,
                         const float* __restrict__ beta,
                         float* __restrict__ out, int N) {
    int i = (blockIdx.x * blockDim.x + threadIdx.x) >> 5;
    if (i >= N) return;
    int lane = threadIdx.x & 31;

    const float4* X = (const float4*)x;
    float bta = beta[0];
    float B = fabsf(bta);
    float inv_i = g_inv[i];

    float4 a = X[i * 32 + lane];

    // self-loop term
    float ss = a.x * a.x + a.y * a.y + a.z * a.z + a.w * a.w;
    #pragma unroll
    for (int o = 16; o; o >>= 1) ss += __shfl_xor_sync(0xffffffffu, ss, o);
    float wv = __expf(bta * (ss * inv_i * inv_i) - B);
    float sum = wv;
    float4 acc = make_float4(wv * a.x, wv * a.y, wv * a.z, wv * a.w);

    int start = g_rowstart[i];
    int end   = g_rowend[i];
    if (start < end) {
        // prefetch first src row
        int s = g_esrc[start];
        float4 v = X[(long long)s * 32 + lane];
        float invs = g_inv[s];
        for (int j = start; j < end; j++) {
            float4 vc = v;
            float invc = invs;
            if (j + 1 < end) {            // prefetch next before the reduce chain
                s = g_esrc[j + 1];
                v = X[(long long)s * 32 + lane];
                invs = g_inv[s];
            }
            float d = a.x * vc.x + a.y * vc.y + a.z * vc.z + a.w * vc.w;
            #pragma unroll
            for (int o = 16; o; o >>= 1) d += __shfl_xor_sync(0xffffffffu, d, o);
            float w = __expf(bta * (d * inv_i * invc) - B);
            sum += w;
            acc.x += w * vc.x;
            acc.y += w * vc.y;
            acc.z += w * vc.z;
            acc.w += w * vc.w;
        }
    }

    float r = 1.0f / sum;
    float4 o4 = make_float4(fmaxf(acc.x * r, 0.0f), fmaxf(acc.y * r, 0.0f),
                            fmaxf(acc.z * r, 0.0f), fmaxf(acc.w * r, 0.0f));
    ((float4*)out)[i * 32 + lane] = o4;
}

// ---------------------------------------------------------------------------
extern "C" void kernel_launch(void* const* d_in, const int* in_sizes, int n_in,
                              void* d_out, int out_size) {
    const float* x    = (const float*)d_in[0];
    const float* beta = (const float*)d_in[1];
    const void*  idx  = d_in[2];
    float* out = (float*)d_out;

    int N = in_sizes[0] / D;
    int E = in_sizes[2] / 2;

    const int T = 256;
    k_detect <<<1, 1>>>((const unsigned int*)idx);
    k_zero   <<<(N + T - 1) / T, T>>>(N);
    k_hist   <<<(E + T - 1) / T, T>>>(idx, E);
    k_alloc  <<<(N + T - 1) / T, T>>>(N);
    k_fill   <<<(E + T - 1) / T, T>>>(idx, E);
    k_invnorm<<<(N * 32 + T - 1) / T, T>>>(x, N);
    k_gather <<<(N * 32 + T - 1) / T, T>>>(x, beta, out, N);
}